// round 5
// baseline (speedup 1.0000x reference)
#include <cuda_runtime.h>
#include <math.h>
#include <stdint.h>

#define B 8
#define D 256
#define NN 1024
#define MM 1024
#define H 8
#define KD 64
#define VD 64
#define QR 512
#define KVR 128

// main-kernel smem (floats): Qfrag 16384 | Kst 2*2048 | Vst 2*2048
#define KST_OFF   16384
#define VST_OFF   20480
#define SMEM_FLOATS 24576
#define SMEM_BYTES (SMEM_FLOATS * 4)
#define OSS 524   // epilogue Os [32][OSS] overlaid at sm+0 (16768 floats)

#define QSCALE 0.1803368801f   // 0.125 * log2(e)

__device__ float g_WqT[QR * D];
__device__ float g_WkvT[KVR * D];
__device__ float g_Q[B * KD * NN * H];   // [b][k][n*8+h], tf32, pre-scaled
__device__ float g_K[B * 32 * 8 * 256];  // fragment-packed per 32-m chunk
__device__ float g_V[B * 32 * 4 * 512];  // fragment-packed per 32-m chunk
__device__ float g_WoP[D * 512];         // Wo packed in A-fragment order

__device__ __forceinline__ float to_tf32(float x) {
    uint32_t u;
    asm("cvt.rna.tf32.f32 %0, %1;" : "=r"(u) : "f"(x));
    return __uint_as_float(u);
}
__device__ __forceinline__ float ex2(float x) {
    float r;
    asm("ex2.approx.f32 %0, %1;" : "=f"(r) : "f"(x));
    return r;
}
__device__ __forceinline__ float rcp(float x) {
    float r;
    asm("rcp.approx.f32 %0, %1;" : "=f"(r) : "f"(x));
    return r;
}
__device__ __forceinline__ void mma8(float* c, const float* a, const float* b) {
    asm volatile(
        "mma.sync.aligned.m16n8k8.row.col.f32.tf32.tf32.f32 "
        "{%0,%1,%2,%3}, {%4,%5,%6,%7}, {%8,%9}, {%0,%1,%2,%3};\n"
        : "+f"(c[0]), "+f"(c[1]), "+f"(c[2]), "+f"(c[3])
        : "r"(__float_as_uint(a[0])), "r"(__float_as_uint(a[1])),
          "r"(__float_as_uint(a[2])), "r"(__float_as_uint(a[3])),
          "r"(__float_as_uint(b[0])), "r"(__float_as_uint(b[1])));
}

// ---------------- kernel 0: pack weights ----------------
__global__ void pack_weights(const float* __restrict__ Wq,
                             const float* __restrict__ Wk,
                             const float* __restrict__ Wv,
                             const float* __restrict__ Wo) {
    int i = blockIdx.x * blockDim.x + threadIdx.x;
    if (i < QR * D) {
        int rk = i / D, d = i % D;
        int k = rk >> 3, h = rk & 7;
        g_WqT[i] = Wq[h * (D * KD) + d * KD + k];
    }
    if (i < KVR * D) {
        int r = i / D, d = i % D;
        g_WkvT[i] = (r < 64) ? Wk[d * KD + r] : Wv[d * VD + (r - 64)];
    }
    if (i < D * 512) {   // Wo fragment pack: [wg16][vh0c16][kc4][lane32][f4]
        int f = i & 3, ln = (i >> 2) & 31, kc = (i >> 7) & 3;
        int vh0c = (i >> 9) & 15, wg = i >> 13;
        int gid = ln >> 2, tig = ln & 3;
        int d = wg * 16 + gid + 8 * (f & 1);
        int vh = vh0c * 32 + kc * 8 + tig + 4 * (f >> 1);
        g_WoP[i] = to_tf32(Wo[d * 512 + vh]);
    }
}

// ---------------- kernel 1: projection GEMM ----------------
template <int MODE>
__global__ void __launch_bounds__(256) proj_gemm(const float* __restrict__ X) {
    const int b = blockIdx.z, r0 = blockIdx.y * 128, n0 = blockIdx.x * 128;
    const float* A = (MODE == 0) ? g_WqT : g_WkvT;
    const float* Xb = X + b * (D * NN);

    __shared__ float As[16 * 136];
    __shared__ float Xs[16 * 128];

    float acc[8][8] = {};
    const int tid = threadIdx.x;
    const int tr = tid >> 4, tn = tid & 15;

    for (int dc = 0; dc < D; dc += 16) {
#pragma unroll
        for (int i = 0; i < 8; i++) {
            int idx = tid + i * 256;
            int rr = idx >> 4, c = idx & 15;
            As[c * 136 + rr] = A[(r0 + rr) * D + dc + c];
        }
#pragma unroll
        for (int i = 0; i < 8; i++) {
            int idx = tid + i * 256;
            int c = idx >> 7, nn = idx & 127;
            Xs[c * 128 + nn] = Xb[(dc + c) * NN + n0 + nn];
        }
        __syncthreads();
#pragma unroll
        for (int c = 0; c < 16; c++) {
            float4 a0 = *(const float4*)&As[c * 136 + tr * 4];
            float4 a1 = *(const float4*)&As[c * 136 + 64 + tr * 4];
            float4 x0 = *(const float4*)&Xs[c * 128 + tn * 4];
            float4 x1 = *(const float4*)&Xs[c * 128 + 64 + tn * 4];
            float ra[8] = {a0.x, a0.y, a0.z, a0.w, a1.x, a1.y, a1.z, a1.w};
            float rx[8] = {x0.x, x0.y, x0.z, x0.w, x1.x, x1.y, x1.z, x1.w};
#pragma unroll
            for (int i = 0; i < 8; i++)
#pragma unroll
                for (int j = 0; j < 8; j++) acc[i][j] += ra[i] * rx[j];
        }
        __syncthreads();
    }

#pragma unroll
    for (int i = 0; i < 8; i++) {
        int r = r0 + tr * 4 + (i & 3) + (i >> 2) * 64;
#pragma unroll
        for (int j = 0; j < 8; j++) {
            int n = n0 + tn * 4 + (j & 3) + (j >> 2) * 64;
            if (MODE == 0) {
                int k = r >> 3, h = r & 7;
                g_Q[b * (KD * NN * H) + k * (NN * H) + n * 8 + h] =
                    to_tf32(acc[i][j] * QSCALE);
            } else {
                float v = to_tf32(acc[i][j]);
                if (r < 64) {
                    int k = r, m = n;
                    int addr = (((b * 32 + (m >> 5)) * 8 + (k >> 3)) << 8)
                             + (((m >> 4) & 1) << 7)
                             + (((m & 7) * 4 + (k & 3)) << 2)
                             + (((k >> 2) & 1) << 1) + ((m >> 3) & 1);
                    g_K[addr] = v;
                } else {
                    int vv = r - 64, m = n, mc = m & 31;
                    int addr = (((b * 32 + (m >> 5)) * 4 + (mc >> 3)) << 9)
                             + ((vv >> 4) << 7)
                             + (((vv & 7) * 4 + (mc & 3)) << 2)
                             + (((mc >> 2) & 1) << 1) + ((vv >> 3) & 1);
                    g_V[addr] = v;
                }
            }
        }
    }
}

// ---------------- kernel 2: fused main (512 threads, 16 warps) ----------------
__global__ void __launch_bounds__(512, 1) mqa_main(float* __restrict__ out) {
    extern __shared__ float sm[];
    float* Qs = sm;

    const int b = blockIdx.y;
    const int n0 = blockIdx.x * 32;
    const int tid = threadIdx.x;
    const int lane = tid & 31;
    const int wgrp = tid >> 5;   // 0..15
    const int gid = lane >> 2;
    const int tig = lane & 3;

    // stage Q into fragment-packed smem: per warp slice 8kc x 128
    {
        const float* Qg = g_Q + b * (KD * NN * H) + n0 * 8;
#pragma unroll
        for (int i = 0; i < 8; i++) {
            int idx = tid + i * 512;         // 4096 float4
            int k = idx >> 6;
            int c4 = (idx & 63) * 4;
            float4 qv = *(const float4*)&Qg[k * (NN * H) + c4];
            int kc = k >> 3, ktig = k & 3, e = (k >> 2) & 1;
#pragma unroll
            for (int t = 0; t < 4; t++) {
                int col = c4 + t;
                int wg = col >> 4, ni = (col >> 3) & 1, gi = col & 7;
                Qs[wg * 1024 + kc * 128 + (gi * 4 + ktig) * 4 + ni * 2 + e] =
                    ((const float*)&qv)[t];
            }
        }
    }

    float Oacc[4][2][4] = {};
    const float* Kg = g_K + b * 65536;
    const float* Vg = g_V + b * 65536;
    const float* Qw = Qs + wgrp * 1024;

    float4 kr = *(const float4*)&Kg[tid * 4];
    float4 vr = *(const float4*)&Vg[tid * 4];

    int s = 0;
    for (int mch = 0; mch < 32; mch++) {
        float* Ks = sm + KST_OFF + s * 2048;
        float* Vs = sm + VST_OFF + s * 2048;
        *(float4*)&Ks[tid * 4] = kr;
        *(float4*)&Vs[tid * 4] = vr;
        __syncthreads();
        if (mch < 31) {
            int nb = (mch + 1) * 2048;
            kr = *(const float4*)&Kg[nb + tid * 4];
            vr = *(const float4*)&Vg[nb + tid * 4];
        }

        // ---- phase 1: logits ----
        float c1[2][2][4] = {};
#pragma unroll
        for (int kc = 0; kc < 8; kc++) {
            float4 a0 = *(const float4*)&Ks[kc * 256 + lane * 4];
            float4 a1 = *(const float4*)&Ks[kc * 256 + 128 + lane * 4];
            float4 q0 = *(const float4*)&Qw[kc * 128 + lane * 4];
            float b0[2] = {q0.x, q0.y}, b1[2] = {q0.z, q0.w};
            mma8(c1[0][0], &a0.x, b0); mma8(c1[0][1], &a0.x, b1);
            mma8(c1[1][0], &a1.x, b0); mma8(c1[1][1], &a1.x, b1);
        }

        // ---- softmax over heads (pre-scaled to exp2 domain) ----
#pragma unroll
        for (int mi = 0; mi < 2; mi++)
#pragma unroll
            for (int ni = 0; ni < 2; ni++) {
                float* cc = c1[mi][ni];
                float e0 = ex2(cc[0]), e1 = ex2(cc[1]);
                float sa = e0 + e1;
                sa += __shfl_xor_sync(0xffffffffu, sa, 1);
                sa += __shfl_xor_sync(0xffffffffu, sa, 2);
                float ra = rcp(sa);
                cc[0] = to_tf32(e0 * ra); cc[1] = to_tf32(e1 * ra);
                float e2 = ex2(cc[2]), e3 = ex2(cc[3]);
                float sb = e2 + e3;
                sb += __shfl_xor_sync(0xffffffffu, sb, 1);
                sb += __shfl_xor_sync(0xffffffffu, sb, 2);
                float rb = rcp(sb);
                cc[2] = to_tf32(e2 * rb); cc[3] = to_tf32(e3 * rb);
            }

        // ---- transpose attn C-frags -> B-frags via shuffles ----
        float bt[4][2][2];
        const int src = tig * 4 + (gid >> 1);
        const bool og = gid & 1;
#pragma unroll
        for (int mi = 0; mi < 2; mi++)
#pragma unroll
            for (int ni = 0; ni < 2; ni++) {
                float* cc = c1[mi][ni];
                float t0 = __shfl_sync(0xffffffffu, cc[0], src);
                float t1 = __shfl_sync(0xffffffffu, cc[1], src);
                float t2 = __shfl_sync(0xffffffffu, cc[2], src);
                float t3 = __shfl_sync(0xffffffffu, cc[3], src);
                float u0 = __shfl_sync(0xffffffffu, cc[0], src + 16);
                float u1 = __shfl_sync(0xffffffffu, cc[1], src + 16);
                float u2 = __shfl_sync(0xffffffffu, cc[2], src + 16);
                float u3 = __shfl_sync(0xffffffffu, cc[3], src + 16);
                bt[2 * mi][ni][0] = og ? t1 : t0;
                bt[2 * mi][ni][1] = og ? u1 : u0;
                bt[2 * mi + 1][ni][0] = og ? t3 : t2;
                bt[2 * mi + 1][ni][1] = og ? u3 : u2;
            }

        // ---- phase 3: O += V @ attn ----
#pragma unroll
        for (int kc3 = 0; kc3 < 4; kc3++) {
            float4 v0 = *(const float4*)&Vs[kc3 * 512 + lane * 4];
            float4 v1 = *(const float4*)&Vs[kc3 * 512 + 128 + lane * 4];
            float4 v2 = *(const float4*)&Vs[kc3 * 512 + 256 + lane * 4];
            float4 v3 = *(const float4*)&Vs[kc3 * 512 + 384 + lane * 4];
#pragma unroll
            for (int ni = 0; ni < 2; ni++) {
                mma8(Oacc[0][ni], &v0.x, bt[kc3][ni]);
                mma8(Oacc[1][ni], &v1.x, bt[kc3][ni]);
                mma8(Oacc[2][ni], &v2.x, bt[kc3][ni]);
                mma8(Oacc[3][ni], &v3.x, bt[kc3][ni]);
            }
        }
        s ^= 1;
    }
    __syncthreads();

    // ---- epilogue: stage O as [n][vh] (tf32) ----
    float* Os = sm;   // [32][OSS]
#pragma unroll
    for (int vi = 0; vi < 4; vi++)
#pragma unroll
        for (int ni = 0; ni < 2; ni++) {
            int nl = wgrp * 2 + ni;
            int v = vi * 16 + gid;
            *(float2*)&Os[nl * OSS + v * 8 + tig * 2] =
                make_float2(to_tf32(Oacc[vi][ni][0]), to_tf32(Oacc[vi][ni][1]));
            *(float2*)&Os[nl * OSS + (v + 8) * 8 + tig * 2] =
                make_float2(to_tf32(Oacc[vi][ni][2]), to_tf32(Oacc[vi][ni][3]));
        }
    __syncthreads();

    // ---- res = Wo @ O via mma, Wo A-fragments direct from gmem (L2) ----
    float racc[4][4] = {};
    const float* WoP = g_WoP + wgrp * 8192;
#pragma unroll 4
    for (int vh0c = 0; vh0c < 16; vh0c++) {
#pragma unroll
        for (int kc = 0; kc < 4; kc++) {
            float4 a = *(const float4*)&WoP[(vh0c * 4 + kc) * 128 + lane * 4];
            int k0 = vh0c * 32 + kc * 8;
#pragma unroll
            for (int ni = 0; ni < 4; ni++) {
                float bf[2];
                bf[0] = Os[(ni * 8 + gid) * OSS + k0 + tig];
                bf[1] = Os[(ni * 8 + gid) * OSS + k0 + tig + 4];
                mma8(racc[ni], &a.x, bf);
            }
        }
    }

    float* ob = out + b * (D * NN);
    const int d = wgrp * 16 + gid;
#pragma unroll
    for (int ni = 0; ni < 4; ni++) {
        *(float2*)&ob[d * NN + n0 + ni * 8 + tig * 2] =
            make_float2(racc[ni][0], racc[ni][1]);
        *(float2*)&ob[(d + 8) * NN + n0 + ni * 8 + tig * 2] =
            make_float2(racc[ni][2], racc[ni][3]);
    }
}

// ---------------- launcher ----------------
extern "C" void kernel_launch(void* const* d_in, const int* in_sizes, int n_in,
                              void* d_out, int out_size) {
    const float* x     = (const float*)d_in[0];
    const float* value = (const float*)d_in[1];
    const float* Wq    = (const float*)d_in[2];
    const float* Wk    = (const float*)d_in[3];
    const float* Wv    = (const float*)d_in[4];
    const float* Wo    = (const float*)d_in[5];
    float* out = (float*)d_out;

    pack_weights<<<512, 256>>>(Wq, Wk, Wv, Wo);
    proj_gemm<0><<<dim3(NN / 128, QR / 128, B), 256>>>(x);
    proj_gemm<1><<<dim3(MM / 128, KVR / 128, B), 256>>>(value);

    cudaFuncSetAttribute(mqa_main, cudaFuncAttributeMaxDynamicSharedMemorySize, SMEM_BYTES);
    mqa_main<<<dim3(NN / 32, B), 512, SMEM_BYTES>>>(out);
}

// round 6
// speedup vs baseline: 1.4017x; 1.4017x over previous
#include <cuda_runtime.h>
#include <math.h>
#include <stdint.h>

#define B 8
#define D 256
#define NN 1024
#define MM 1024
#define H 8
#define KD 64
#define VD 64
#define KVR 128

// smem (floats): 4 stages x (K 2048 | V 2048) = 16384 | Xs/Qsm @16384
#define XS_OFF 16384
#define XSP 40              // Xs [256][40]
#define QSM_OFF 16384
#define QSP 34              // Qsm [512][34]
#define SMEM_FLOATS (QSM_OFF + 512 * QSP)   // 33792
#define SMEM_BYTES (SMEM_FLOATS * 4)
#define OSS 524             // epilogue Os [32][OSS] @ sm+0

#define QSCALE 0.1803368801f   // 0.125 * log2(e)

__device__ float g_WkvT[KVR * D];
__device__ float g_WqP[512 * D];         // Wq A-fragment packed, pre-scaled tf32
__device__ float g_K[B * 32 * 8 * 256];  // K fragment-packed per 32-m chunk
__device__ float g_V[B * 32 * 4 * 512];  // V fragment-packed per 32-m chunk
__device__ float g_WoP[D * 512];         // Wo A-fragment packed, tf32

__device__ __forceinline__ float to_tf32(float x) {
    uint32_t u;
    asm("cvt.rna.tf32.f32 %0, %1;" : "=r"(u) : "f"(x));
    return __uint_as_float(u);
}
__device__ __forceinline__ float ex2(float x) {
    float r; asm("ex2.approx.f32 %0, %1;" : "=f"(r) : "f"(x)); return r;
}
__device__ __forceinline__ float rcp(float x) {
    float r; asm("rcp.approx.f32 %0, %1;" : "=f"(r) : "f"(x)); return r;
}
__device__ __forceinline__ void mma8(float* c, const float* a, const float* b) {
    asm volatile(
        "mma.sync.aligned.m16n8k8.row.col.f32.tf32.tf32.f32 "
        "{%0,%1,%2,%3}, {%4,%5,%6,%7}, {%8,%9}, {%0,%1,%2,%3};\n"
        : "+f"(c[0]), "+f"(c[1]), "+f"(c[2]), "+f"(c[3])
        : "r"(__float_as_uint(a[0])), "r"(__float_as_uint(a[1])),
          "r"(__float_as_uint(a[2])), "r"(__float_as_uint(a[3])),
          "r"(__float_as_uint(b[0])), "r"(__float_as_uint(b[1])));
}
__device__ __forceinline__ void cp16(uint32_t dst, const float* src) {
    asm volatile("cp.async.cg.shared.global [%0], [%1], 16;\n"
                 :: "r"(dst), "l"(src));
}
#define CP_COMMIT() asm volatile("cp.async.commit_group;\n" ::)
#define CP_WAIT(n)  asm volatile("cp.async.wait_group %0;\n" :: "n"(n))

// ---------------- kernel 0: pack weights ----------------
__global__ void pack_weights(const float* __restrict__ Wq,
                             const float* __restrict__ Wk,
                             const float* __restrict__ Wv,
                             const float* __restrict__ Wo) {
    int i = blockIdx.x * blockDim.x + threadIdx.x;
    if (i < KVR * D) {
        int r = i / D, d = i % D;
        g_WkvT[i] = (r < 64) ? Wk[d * KD + r] : Wv[d * VD + (r - 64)];
    }
    if (i < 512 * D) {   // WqP: [w16][kc32][mi2][lane32][e4]
        int e = i & 3, ln = (i >> 2) & 31, mi = (i >> 7) & 1;
        int kc = (i >> 8) & 31, w = (i >> 13) & 15;
        int gid = ln >> 2, tig = ln & 3;
        int rk = w * 32 + mi * 16 + gid + 8 * (e & 1);
        int d = kc * 8 + tig + 4 * (e >> 1);
        int kq = rk >> 3, h = rk & 7;
        g_WqP[i] = to_tf32(Wq[h * (D * KD) + d * KD + kq] * QSCALE);
    }
    if (i < D * 512) {   // WoP: [wg16][vh0c16][kc4][lane32][f4]
        int f = i & 3, ln = (i >> 2) & 31, kc = (i >> 7) & 3;
        int vh0c = (i >> 9) & 15, wg = i >> 13;
        int gid = ln >> 2, tig = ln & 3;
        int d = wg * 16 + gid + 8 * (f & 1);
        int vh = vh0c * 32 + kc * 8 + tig + 4 * (f >> 1);
        g_WoP[i] = to_tf32(Wo[d * 512 + vh]);
    }
}

// ---------------- kernel 1: K/V projection GEMM ----------------
__global__ void __launch_bounds__(256) proj_kv(const float* __restrict__ X) {
    const int b = blockIdx.z, n0 = blockIdx.x * 128;
    const float* A = g_WkvT;
    const float* Xb = X + b * (D * NN);

    __shared__ float As[16 * 136];
    __shared__ float Xs[16 * 128];

    float acc[8][8] = {};
    const int tid = threadIdx.x;
    const int tr = tid >> 4, tn = tid & 15;

    for (int dc = 0; dc < D; dc += 16) {
#pragma unroll
        for (int i = 0; i < 8; i++) {
            int idx = tid + i * 256;
            int rr = idx >> 4, c = idx & 15;
            As[c * 136 + rr] = A[rr * D + dc + c];
        }
#pragma unroll
        for (int i = 0; i < 8; i++) {
            int idx = tid + i * 256;
            int c = idx >> 7, nn = idx & 127;
            Xs[c * 128 + nn] = Xb[(dc + c) * NN + n0 + nn];
        }
        __syncthreads();
#pragma unroll
        for (int c = 0; c < 16; c++) {
            float4 a0 = *(const float4*)&As[c * 136 + tr * 4];
            float4 a1 = *(const float4*)&As[c * 136 + 64 + tr * 4];
            float4 x0 = *(const float4*)&Xs[c * 128 + tn * 4];
            float4 x1 = *(const float4*)&Xs[c * 128 + 64 + tn * 4];
            float ra[8] = {a0.x, a0.y, a0.z, a0.w, a1.x, a1.y, a1.z, a1.w};
            float rx[8] = {x0.x, x0.y, x0.z, x0.w, x1.x, x1.y, x1.z, x1.w};
#pragma unroll
            for (int i = 0; i < 8; i++)
#pragma unroll
                for (int j = 0; j < 8; j++) acc[i][j] += ra[i] * rx[j];
        }
        __syncthreads();
    }

#pragma unroll
    for (int i = 0; i < 8; i++) {
        int r = tr * 4 + (i & 3) + (i >> 2) * 64;
#pragma unroll
        for (int j = 0; j < 8; j++) {
            int n = n0 + tn * 4 + (j & 3) + (j >> 2) * 64;
            float v = to_tf32(acc[i][j]);
            if (r < 64) {
                int k = r, m = n;
                int addr = (((b * 32 + (m >> 5)) * 8 + (k >> 3)) << 8)
                         + (((m >> 4) & 1) << 7)
                         + (((m & 7) * 4 + (k & 3)) << 2)
                         + (((k >> 2) & 1) << 1) + ((m >> 3) & 1);
                g_K[addr] = v;
            } else {
                int vv = r - 64, m = n, mc = m & 31;
                int addr = (((b * 32 + (m >> 5)) * 4 + (mc >> 3)) << 9)
                         + ((vv >> 4) << 7)
                         + (((vv & 7) * 4 + (mc & 3)) << 2)
                         + (((mc >> 2) & 1) << 1) + ((vv >> 3) & 1);
                g_V[addr] = v;
            }
        }
    }
}

// ---------------- kernel 2: fused main (Q-proj prologue + attention) ----------------
__global__ void __launch_bounds__(512, 1) mqa_main(const float* __restrict__ x,
                                                   float* __restrict__ out) {
    extern __shared__ float sm[];

    const int b = blockIdx.y;
    const int n0 = blockIdx.x * 32;
    const int tid = threadIdx.x;
    const int lane = tid & 31;
    const int wgrp = tid >> 5;   // 0..15
    const int gid = lane >> 2;
    const int tig = lane & 3;

    const float* Kg = g_K + b * 65536;
    const float* Vg = g_V + b * 65536;

    // issue first 3 K/V stages via cp.async
    const uint32_t smem_u32 = (uint32_t)__cvta_generic_to_shared(sm);
#pragma unroll
    for (int s = 0; s < 3; s++) {
        uint32_t dk = smem_u32 + (s * 4096 + tid * 4) * 4;
        cp16(dk, Kg + s * 2048 + tid * 4);
        cp16(dk + 2048 * 4, Vg + s * 2048 + tid * 4);
        CP_COMMIT();
    }

    // ---- prologue: Q projection via MMA ----
    float Qreg[8][4];
    {
        float* Xs = sm + XS_OFF;   // [256][40]
        const float* Xb = x + b * (D * NN);
#pragma unroll
        for (int i = 0; i < 16; i++) {
            int idx = tid + i * 512;
            int d = idx >> 5, n = idx & 31;
            Xs[d * XSP + n] = to_tf32(Xb[d * NN + n0 + n]);
        }
        __syncthreads();

        float qa[2][4][4] = {};
        const float* WqPw = g_WqP + wgrp * 8192;
#pragma unroll 4
        for (int kc = 0; kc < 32; kc++) {
            float4 a0 = *(const float4*)&WqPw[kc * 256 + lane * 4];
            float4 a1 = *(const float4*)&WqPw[kc * 256 + 128 + lane * 4];
            float bf[4][2];
#pragma unroll
            for (int ni = 0; ni < 4; ni++) {
                bf[ni][0] = Xs[(kc * 8 + tig) * XSP + ni * 8 + gid];
                bf[ni][1] = Xs[(kc * 8 + tig + 4) * XSP + ni * 8 + gid];
            }
#pragma unroll
            for (int ni = 0; ni < 4; ni++) {
                mma8(qa[0][ni], &a0.x, bf[ni]);
                mma8(qa[1][ni], &a1.x, bf[ni]);
            }
        }
        __syncthreads();   // Xs reads done before Qsm overwrites

        float* Qsm = sm + QSM_OFF;   // [512][34]
#pragma unroll
        for (int mi = 0; mi < 2; mi++)
#pragma unroll
            for (int ni = 0; ni < 4; ni++) {
                int row = wgrp * 32 + mi * 16 + gid;
                int col = ni * 8 + tig * 2;
                *(float2*)&Qsm[row * QSP + col] =
                    make_float2(to_tf32(qa[mi][ni][0]), to_tf32(qa[mi][ni][1]));
                *(float2*)&Qsm[(row + 8) * QSP + col] =
                    make_float2(to_tf32(qa[mi][ni][2]), to_tf32(qa[mi][ni][3]));
            }
        __syncthreads();

        // load persistent Q B-fragments: col = wgrp*16 + gid + 8*ni, k = kc*8+tig+4e
#pragma unroll
        for (int kc = 0; kc < 8; kc++)
#pragma unroll
            for (int ni = 0; ni < 2; ni++)
#pragma unroll
                for (int e = 0; e < 2; e++) {
                    int k = kc * 8 + tig + 4 * e;
                    Qreg[kc][ni * 2 + e] = Qsm[(k * 8 + gid) * QSP + wgrp * 2 + ni];
                }
    }

    float Oacc[4][2][4] = {};
    const int src = tig * 4 + (gid >> 1);
    const bool og = gid & 1;

    for (int mch = 0; mch < 32; mch++) {
        CP_WAIT(2);
        __syncthreads();

        // issue stage mch+3
        if (mch + 3 < 32) {
            int s = (mch + 3) & 3;
            uint32_t dk = smem_u32 + (s * 4096 + tid * 4) * 4;
            cp16(dk, Kg + (mch + 3) * 2048 + tid * 4);
            cp16(dk + 2048 * 4, Vg + (mch + 3) * 2048 + tid * 4);
        }
        CP_COMMIT();

        const float* Ks = sm + (mch & 3) * 4096;
        const float* Vs = Ks + 2048;

        // ---- phase 1: logits (Q from registers) ----
        float c1[2][2][4] = {};
#pragma unroll
        for (int kc = 0; kc < 8; kc++) {
            float4 a0 = *(const float4*)&Ks[kc * 256 + lane * 4];
            float4 a1 = *(const float4*)&Ks[kc * 256 + 128 + lane * 4];
            mma8(c1[0][0], &a0.x, &Qreg[kc][0]);
            mma8(c1[0][1], &a0.x, &Qreg[kc][2]);
            mma8(c1[1][0], &a1.x, &Qreg[kc][0]);
            mma8(c1[1][1], &a1.x, &Qreg[kc][2]);
        }

        // ---- softmax over heads ----
#pragma unroll
        for (int mi = 0; mi < 2; mi++)
#pragma unroll
            for (int ni = 0; ni < 2; ni++) {
                float* cc = c1[mi][ni];
                float e0 = ex2(cc[0]), e1 = ex2(cc[1]);
                float sa = e0 + e1;
                sa += __shfl_xor_sync(0xffffffffu, sa, 1);
                sa += __shfl_xor_sync(0xffffffffu, sa, 2);
                float ra = rcp(sa);
                cc[0] = to_tf32(e0 * ra); cc[1] = to_tf32(e1 * ra);
                float e2 = ex2(cc[2]), e3 = ex2(cc[3]);
                float sb = e2 + e3;
                sb += __shfl_xor_sync(0xffffffffu, sb, 1);
                sb += __shfl_xor_sync(0xffffffffu, sb, 2);
                float rb = rcp(sb);
                cc[2] = to_tf32(e2 * rb); cc[3] = to_tf32(e3 * rb);
            }

        // ---- phase 3: transpose (per kc3) + O += V @ attn ----
#pragma unroll
        for (int kc3 = 0; kc3 < 4; kc3++) {
            const int mi = kc3 >> 1, p = kc3 & 1;
            float bt[2][2];
#pragma unroll
            for (int ni = 0; ni < 2; ni++) {
                float lo = c1[mi][ni][2 * p], hi = c1[mi][ni][2 * p + 1];
                float t0 = __shfl_sync(0xffffffffu, lo, src);
                float t1 = __shfl_sync(0xffffffffu, hi, src);
                float u0 = __shfl_sync(0xffffffffu, lo, src + 16);
                float u1 = __shfl_sync(0xffffffffu, hi, src + 16);
                bt[ni][0] = og ? t1 : t0;
                bt[ni][1] = og ? u1 : u0;
            }
            float4 v0 = *(const float4*)&Vs[kc3 * 512 + lane * 4];
            float4 v1 = *(const float4*)&Vs[kc3 * 512 + 128 + lane * 4];
            float4 v2 = *(const float4*)&Vs[kc3 * 512 + 256 + lane * 4];
            float4 v3 = *(const float4*)&Vs[kc3 * 512 + 384 + lane * 4];
#pragma unroll
            for (int ni = 0; ni < 2; ni++) {
                mma8(Oacc[0][ni], &v0.x, bt[ni]);
                mma8(Oacc[1][ni], &v1.x, bt[ni]);
                mma8(Oacc[2][ni], &v2.x, bt[ni]);
                mma8(Oacc[3][ni], &v3.x, bt[ni]);
            }
        }
    }
    CP_WAIT(0);
    __syncthreads();

    // ---- epilogue: stage O as [n][vh] (tf32) ----
    float* Os = sm;   // [32][OSS]
#pragma unroll
    for (int vi = 0; vi < 4; vi++)
#pragma unroll
        for (int ni = 0; ni < 2; ni++) {
            int nl = wgrp * 2 + ni;
            int v = vi * 16 + gid;
            *(float2*)&Os[nl * OSS + v * 8 + tig * 2] =
                make_float2(to_tf32(Oacc[vi][ni][0]), to_tf32(Oacc[vi][ni][1]));
            *(float2*)&Os[nl * OSS + (v + 8) * 8 + tig * 2] =
                make_float2(to_tf32(Oacc[vi][ni][2]), to_tf32(Oacc[vi][ni][3]));
        }
    __syncthreads();

    // ---- res = Wo @ O via mma, Wo A-fragments from gmem (L2) ----
    float racc[4][4] = {};
    const float* WoP = g_WoP + wgrp * 8192;
#pragma unroll 4
    for (int vh0c = 0; vh0c < 16; vh0c++) {
#pragma unroll
        for (int kc = 0; kc < 4; kc++) {
            float4 a = *(const float4*)&WoP[(vh0c * 4 + kc) * 128 + lane * 4];
            int k0 = vh0c * 32 + kc * 8;
#pragma unroll
            for (int ni = 0; ni < 4; ni++) {
                float bf[2];
                bf[0] = Os[(ni * 8 + gid) * OSS + k0 + tig];
                bf[1] = Os[(ni * 8 + gid) * OSS + k0 + tig + 4];
                mma8(racc[ni], &a.x, bf);
            }
        }
    }

    float* ob = out + b * (D * NN);
    const int d = wgrp * 16 + gid;
#pragma unroll
    for (int ni = 0; ni < 4; ni++) {
        *(float2*)&ob[d * NN + n0 + ni * 8 + tig * 2] =
            make_float2(racc[ni][0], racc[ni][1]);
        *(float2*)&ob[(d + 8) * NN + n0 + ni * 8 + tig * 2] =
            make_float2(racc[ni][2], racc[ni][3]);
    }
}

// ---------------- launcher ----------------
extern "C" void kernel_launch(void* const* d_in, const int* in_sizes, int n_in,
                              void* d_out, int out_size) {
    const float* x     = (const float*)d_in[0];
    const float* value = (const float*)d_in[1];
    const float* Wq    = (const float*)d_in[2];
    const float* Wk    = (const float*)d_in[3];
    const float* Wv    = (const float*)d_in[4];
    const float* Wo    = (const float*)d_in[5];
    float* out = (float*)d_out;

    pack_weights<<<512, 256>>>(Wq, Wk, Wv, Wo);
    proj_kv<<<dim3(MM / 128, 1, B), 256>>>(value);

    cudaFuncSetAttribute(mqa_main, cudaFuncAttributeMaxDynamicSharedMemorySize, SMEM_BYTES);
    mqa_main<<<dim3(NN / 32, B), 512, SMEM_BYTES>>>(x, out);
}